// round 1
// baseline (speedup 1.0000x reference)
#include <cuda_runtime.h>
#include <math.h>
#include <float.h>

// ---------------- problem constants ----------------
#define NN_   8192      // nodes
#define E1_   131072    // node-graph edges (= trace rows)
#define E2_   524288    // line-graph edges
#define DIN   256       // layer1 channels (4 heads x 64)
#define DED   128       // layer2 channels (4 heads x 32)
#define EPSV  1e-16f

// ---------------- scratch (static device, no allocs) ----------------
__device__ float g_node   [(size_t)NN_ * DIN];     // concat(x_node, x_log)
__device__ float g_xl     [(size_t)NN_ * DIN];
__device__ float g_xr     [(size_t)NN_ * DIN];
__device__ float g_e1     [(size_t)E1_ * DIN];     // trace @ We   (134 MB)
__device__ float g_alpha1 [(size_t)E1_ * 4];
__device__ float g_amax1  [(size_t)NN_ * 4];
__device__ float g_den1   [(size_t)NN_ * 4];
__device__ float g_nodeout[(size_t)NN_ * DIN];
__device__ float g_xl2    [(size_t)E1_ * DED];
__device__ float g_xr2    [(size_t)E1_ * DED];
__device__ float g_gfeat  [(size_t)NN_ * DED];     // node_out @ We2
__device__ float g_alpha2 [(size_t)E2_ * 4];
__device__ float g_amax2  [(size_t)E1_ * 4];
__device__ float g_den2   [(size_t)E1_ * 4];

// ---------------- helpers ----------------
__device__ __forceinline__ void atomicMaxFloat(float* addr, float val) {
    if (val >= 0.f) atomicMax((int*)addr, __float_as_int(val));
    else            atomicMin((unsigned int*)addr, __float_as_uint(val));
}

__device__ __forceinline__ float lrelu02(float x) {
    return x > 0.f ? x : 0.2f * x;
}

// ---------------- generic tiled fp32 GEMM: C = A[MxK] @ W[KxN] + bias ----------------
#define BM 64
#define BN 64
#define BK 16
__global__ __launch_bounds__(256) void gemm_bias(
    const float* __restrict__ A, const float* __restrict__ W,
    const float* __restrict__ bias, float* __restrict__ C,
    int M, int Ncol, int K)
{
    __shared__ float As[BK][BM + 1];
    __shared__ float Bs[BK][BN];
    const int bm = blockIdx.y * BM, bn = blockIdx.x * BN;
    const int tid = threadIdx.x;
    const int tr = tid / 16, tc = tid % 16;
    float acc[4][4] = {};

    for (int k0 = 0; k0 < K; k0 += BK) {
#pragma unroll
        for (int i = 0; i < 4; i++) {
            int idx = tid + i * 256;           // 0..1023
            int m = idx / BK, kk = idx % BK;
            As[kk][m] = A[(size_t)(bm + m) * K + k0 + kk];
        }
#pragma unroll
        for (int i = 0; i < 4; i++) {
            int idx = tid + i * 256;
            int kk = idx / BN, n = idx % BN;
            Bs[kk][n] = W[(size_t)(k0 + kk) * Ncol + bn + n];
        }
        __syncthreads();
#pragma unroll
        for (int kk = 0; kk < BK; kk++) {
            float a[4], b[4];
#pragma unroll
            for (int i = 0; i < 4; i++) a[i] = As[kk][tr * 4 + i];
#pragma unroll
            for (int j = 0; j < 4; j++) b[j] = Bs[kk][tc * 4 + j];
#pragma unroll
            for (int i = 0; i < 4; i++)
#pragma unroll
                for (int j = 0; j < 4; j++) acc[i][j] += a[i] * b[j];
        }
        __syncthreads();
    }
#pragma unroll
    for (int i = 0; i < 4; i++) {
        int m = bm + tr * 4 + i;
#pragma unroll
        for (int j = 0; j < 4; j++) {
            int n = bn + tc * 4 + j;
            C[(size_t)m * Ncol + n] = acc[i][j] + (bias ? bias[n] : 0.f);
        }
    }
}

// ---------------- misc elementwise kernels ----------------
__global__ void concat_kernel(const float* __restrict__ x_node,
                              const float* __restrict__ x_log)
{
    size_t idx = (size_t)blockIdx.x * blockDim.x + threadIdx.x;   // NN_*256
    if (idx >= (size_t)NN_ * DIN) return;
    int i = (int)(idx >> 8), c = (int)(idx & 255);
    g_node[idx] = (c < 128) ? x_node[(size_t)i * 128 + c]
                            : x_log[(size_t)i * 128 + (c - 128)];
}

__global__ void init_softmax1_kernel() {
    int idx = blockIdx.x * blockDim.x + threadIdx.x;
    if (idx >= NN_ * 4) return;
    g_amax1[idx] = -FLT_MAX;
    g_den1[idx]  = 0.f;
}

__global__ void init_softmax2_kernel() {
    int idx = blockIdx.x * blockDim.x + threadIdx.x;
    if (idx >= E1_ * 4) return;
    g_amax2[idx] = -FLT_MAX;
    g_den2[idx]  = 0.f;
}

__global__ void init_nodeout_kernel(const float* __restrict__ bias) {
    size_t idx = (size_t)blockIdx.x * blockDim.x + threadIdx.x;
    if (idx >= (size_t)NN_ * DIN) return;
    g_nodeout[idx] = bias[idx & 255];
}

// ---------------- layer 1 edge kernels (warp per edge) ----------------
__global__ __launch_bounds__(256) void alpha1_kernel(const int* __restrict__ adj,
                                                     const float* __restrict__ att)
{
    int warp = (blockIdx.x * blockDim.x + threadIdx.x) >> 5;
    int lane = threadIdx.x & 31;
    if (warp >= E1_) return;
    int src = adj[warp], dst = adj[E1_ + warp];
    const float* xl = g_xl + (size_t)src * DIN;
    const float* xr = g_xr + (size_t)dst * DIN;
    const float* ee = g_e1 + (size_t)warp * DIN;
    float p[4];
#pragma unroll
    for (int h = 0; h < 4; h++) {
        p[h] = 0.f;
#pragma unroll
        for (int jj = 0; jj < 2; jj++) {
            int c = h * 64 + jj * 32 + lane;
            float m = lrelu02(xl[c] + xr[c] + ee[c]);
            p[h] += m * att[c];
        }
    }
#pragma unroll
    for (int h = 0; h < 4; h++) {
#pragma unroll
        for (int off = 16; off > 0; off >>= 1)
            p[h] += __shfl_xor_sync(0xffffffff, p[h], off);
    }
    if (lane < 4) {
        g_alpha1[(size_t)warp * 4 + lane] = p[lane];
        atomicMaxFloat(&g_amax1[(size_t)dst * 4 + lane], p[lane]);
    }
}

__global__ void exp1_kernel(const int* __restrict__ adj) {
    int idx = blockIdx.x * blockDim.x + threadIdx.x;
    if (idx >= E1_ * 4) return;
    int e = idx >> 2, h = idx & 3;
    int dst = adj[E1_ + e];
    float ex = expf(g_alpha1[idx] - g_amax1[dst * 4 + h]);
    g_alpha1[idx] = ex;
    atomicAdd(&g_den1[dst * 4 + h], ex);
}

__global__ __launch_bounds__(256) void agg1_kernel(const int* __restrict__ adj) {
    int warp = (blockIdx.x * blockDim.x + threadIdx.x) >> 5;
    int lane = threadIdx.x & 31;
    if (warp >= E1_) return;
    int src = adj[warp], dst = adj[E1_ + warp];
    float a[4];
#pragma unroll
    for (int h = 0; h < 4; h++)
        a[h] = g_alpha1[(size_t)warp * 4 + h] / (g_den1[(size_t)dst * 4 + h] + EPSV);
    const float* xl = g_xl + (size_t)src * DIN;
    float* out = g_nodeout + (size_t)dst * DIN;
#pragma unroll
    for (int h = 0; h < 4; h++) {
#pragma unroll
        for (int jj = 0; jj < 2; jj++) {
            int c = h * 64 + jj * 32 + lane;
            atomicAdd(&out[c], a[h] * xl[c]);
        }
    }
}

// ---------------- layer 2 edge kernels ----------------
__global__ __launch_bounds__(256) void alpha2_kernel(const int* __restrict__ adj,
                                                     const int* __restrict__ efea,
                                                     const float* __restrict__ att)
{
    int warp = (blockIdx.x * blockDim.x + threadIdx.x) >> 5;
    int lane = threadIdx.x & 31;
    if (warp >= E2_) return;
    int src = adj[warp], dst = adj[E2_ + warp];
    int ef = efea[warp];
    const float* xl = g_xl2 + (size_t)src * DED;
    const float* xr = g_xr2 + (size_t)dst * DED;
    const float* ee = g_gfeat + (size_t)ef * DED;
    float p[4];
#pragma unroll
    for (int h = 0; h < 4; h++) {
        int c = h * 32 + lane;
        float m = lrelu02(xl[c] + xr[c] + ee[c]);
        p[h] = m * att[c];
    }
#pragma unroll
    for (int h = 0; h < 4; h++) {
#pragma unroll
        for (int off = 16; off > 0; off >>= 1)
            p[h] += __shfl_xor_sync(0xffffffff, p[h], off);
    }
    if (lane < 4) {
        g_alpha2[(size_t)warp * 4 + lane] = p[lane];
        atomicMaxFloat(&g_amax2[(size_t)dst * 4 + lane], p[lane]);
    }
}

__global__ void exp2_kernel(const int* __restrict__ adj) {
    size_t idx = (size_t)blockIdx.x * blockDim.x + threadIdx.x;
    if (idx >= (size_t)E2_ * 4) return;
    int e = (int)(idx >> 2), h = (int)(idx & 3);
    int dst = adj[E2_ + e];
    float ex = expf(g_alpha2[idx] - g_amax2[(size_t)dst * 4 + h]);
    g_alpha2[idx] = ex;
    atomicAdd(&g_den2[(size_t)dst * 4 + h], ex);
}

// split node_out into xn / xlg regions of d_out and seed xt region with bias2
__global__ void out_split_kernel(float* __restrict__ out, const float* __restrict__ bias2) {
    size_t idx = (size_t)blockIdx.x * blockDim.x + threadIdx.x;
    const size_t XN = (size_t)NN_ * 128;
    const size_t XT = (size_t)E1_ * 128;
    if (idx >= XN + XT + XN) return;
    if (idx < XN) {
        int i = (int)(idx >> 7), c = (int)(idx & 127);
        out[idx] = g_nodeout[(size_t)i * DIN + c];
    } else if (idx < XN + XT) {
        out[idx] = bias2[idx & 127];
    } else {
        size_t r = idx - (XN + XT);
        int i = (int)(r >> 7), c = (int)(r & 127);
        out[idx] = g_nodeout[(size_t)i * DIN + 128 + c];
    }
}

__global__ __launch_bounds__(256) void agg2_kernel(const int* __restrict__ adj,
                                                   float* __restrict__ out_xt)
{
    int warp = (blockIdx.x * blockDim.x + threadIdx.x) >> 5;
    int lane = threadIdx.x & 31;
    if (warp >= E2_) return;
    int src = adj[warp], dst = adj[E2_ + warp];
    float a[4];
#pragma unroll
    for (int h = 0; h < 4; h++)
        a[h] = g_alpha2[(size_t)warp * 4 + h] / (g_den2[(size_t)dst * 4 + h] + EPSV);
    const float* xl = g_xl2 + (size_t)src * DED;
    float* out = out_xt + (size_t)dst * DED;
#pragma unroll
    for (int h = 0; h < 4; h++) {
        int c = h * 32 + lane;
        atomicAdd(&out[c], a[h] * xl[c]);
    }
}

// ---------------- launch ----------------
extern "C" void kernel_launch(void* const* d_in, const int* in_sizes, int n_in,
                              void* d_out, int out_size)
{
    const float* x_node   = (const float*)d_in[0];
    const float* x_trace  = (const float*)d_in[1];
    const float* x_log    = (const float*)d_in[2];
    const int*   node_adj = (const int*)d_in[3];
    const int*   edge_adj = (const int*)d_in[4];
    const int*   edge_efea= (const int*)d_in[5];
    const float* n2n_Wl   = (const float*)d_in[6];
    const float* n2n_bl   = (const float*)d_in[7];
    const float* n2n_Wr   = (const float*)d_in[8];
    const float* n2n_br   = (const float*)d_in[9];
    const float* n2n_We   = (const float*)d_in[10];
    const float* n2n_att  = (const float*)d_in[11];
    const float* n2n_bias = (const float*)d_in[12];
    const float* e2n_Wl   = (const float*)d_in[13];
    const float* e2n_bl   = (const float*)d_in[14];
    const float* e2n_Wr   = (const float*)d_in[15];
    const float* e2n_br   = (const float*)d_in[16];
    const float* e2n_We   = (const float*)d_in[17];
    const float* e2n_att  = (const float*)d_in[18];
    const float* e2n_bias = (const float*)d_in[19];
    float* out = (float*)d_out;

    float* p_node;    cudaGetSymbolAddress((void**)&p_node,    g_node);
    float* p_xl;      cudaGetSymbolAddress((void**)&p_xl,      g_xl);
    float* p_xr;      cudaGetSymbolAddress((void**)&p_xr,      g_xr);
    float* p_e1;      cudaGetSymbolAddress((void**)&p_e1,      g_e1);
    float* p_nodeout; cudaGetSymbolAddress((void**)&p_nodeout, g_nodeout);
    float* p_xl2;     cudaGetSymbolAddress((void**)&p_xl2,     g_xl2);
    float* p_xr2;     cudaGetSymbolAddress((void**)&p_xr2,     g_xr2);
    float* p_g;       cudaGetSymbolAddress((void**)&p_g,       g_gfeat);

    // ---- prep ----
    concat_kernel<<<(NN_ * DIN) / 256, 256>>>(x_node, x_log);
    init_softmax1_kernel<<<(NN_ * 4) / 256, 256>>>();
    init_softmax2_kernel<<<(E1_ * 4) / 256, 256>>>();
    init_nodeout_kernel<<<(NN_ * DIN) / 256, 256>>>(n2n_bias);

    // ---- layer-1 GEMMs ----
    {
        dim3 g1(DIN / BN, NN_ / BM);
        gemm_bias<<<g1, 256>>>(p_node, n2n_Wl, n2n_bl, p_xl, NN_, DIN, DIN);
        gemm_bias<<<g1, 256>>>(p_node, n2n_Wr, n2n_br, p_xr, NN_, DIN, DIN);
        dim3 ge(DIN / BN, E1_ / BM);
        gemm_bias<<<ge, 256>>>(x_trace, n2n_We, nullptr, p_e1, E1_, DIN, 128);
        // layer-2 source/target transforms can start now too (depend only on trace)
        dim3 g2(DED / BN, E1_ / BM);
        gemm_bias<<<g2, 256>>>(x_trace, e2n_Wl, e2n_bl, p_xl2, E1_, DED, DED);
        gemm_bias<<<g2, 256>>>(x_trace, e2n_Wr, e2n_br, p_xr2, E1_, DED, DED);
    }

    // ---- layer-1 attention + softmax + aggregate ----
    alpha1_kernel<<<E1_ / 8, 256>>>(node_adj, n2n_att);
    exp1_kernel<<<(E1_ * 4) / 256, 256>>>(node_adj);
    agg1_kernel<<<E1_ / 8, 256>>>(node_adj);

    // ---- layer-2: edge attr = node_out[efea] @ We2 == gather of g = node_out @ We2 ----
    {
        dim3 gg(DED / BN, NN_ / BM);
        gemm_bias<<<gg, 256>>>(p_nodeout, e2n_We, nullptr, p_g, NN_, DED, DIN);
    }

    alpha2_kernel<<<E2_ / 8, 256>>>(edge_adj, edge_efea, e2n_att);
    exp2_kernel<<<(E2_ * 4) / 256, 256>>>(edge_adj);

    {
        size_t total = (size_t)NN_ * 128 * 2 + (size_t)E1_ * 128;
        out_split_kernel<<<(unsigned)((total + 255) / 256), 256>>>(out, e2n_bias);
    }
    agg2_kernel<<<E2_ / 8, 256>>>(edge_adj, out + (size_t)NN_ * 128);
}

// round 3
// speedup vs baseline: 1.3688x; 1.3688x over previous
#include <cuda_runtime.h>
#include <stdint.h>
#include <math.h>
#include <float.h>

// ---------------- problem constants ----------------
#define NN_   8192      // nodes
#define E1_   131072    // node-graph edges (= trace rows)
#define E2_   524288    // line-graph edges
#define DIN   256       // layer1 channels (4 heads x 64)
#define DED   128       // layer2 channels (4 heads x 32)
#define EPSV  1e-16f

// ---------------- scratch (static device, no allocs) ----------------
__device__ float g_node   [(size_t)NN_ * DIN];     // concat(x_node, x_log)
__device__ float g_xl     [(size_t)NN_ * DIN];
__device__ float g_xr     [(size_t)NN_ * DIN];
__device__ float g_e1     [(size_t)E1_ * DIN];     // trace @ We
__device__ float g_alpha1 [(size_t)E1_ * 4];
__device__ float g_amax1  [(size_t)NN_ * 4];
__device__ float g_den1   [(size_t)NN_ * 4];
__device__ float g_nodeout[(size_t)NN_ * DIN];
__device__ float g_xl2    [(size_t)E1_ * DED];
__device__ float g_xr2    [(size_t)E1_ * DED];
__device__ float g_gfeat  [(size_t)NN_ * DED];     // node_out @ We2
__device__ float g_alpha2 [(size_t)E2_ * 4];
__device__ float g_amax2  [(size_t)E1_ * 4];
__device__ float g_den2   [(size_t)E1_ * 4];

// ---------------- helpers ----------------
__device__ __forceinline__ void atomicMaxFloat(float* addr, float val) {
    if (val >= 0.f) atomicMax((int*)addr, __float_as_int(val));
    else            atomicMin((unsigned int*)addr, __float_as_uint(val));
}

__device__ __forceinline__ float lrelu02(float x) {
    return x > 0.f ? x : 0.2f * x;
}

__device__ __forceinline__ float to_tf32(float v) {
    uint32_t t;
    asm("cvt.rna.tf32.f32 %0, %1;" : "=r"(t) : "f"(v));
    return __uint_as_float(t);
}

// ---------------- tf32 tensor-core GEMM: C = A[MxK] @ W[KxN] + bias ----------------
// Block tile 128x128, 8 warps, warp tile 64x32, k-chunk 32.
// mma.sync m16n8k8 tf32. Smem layouts are bank-conflict-free for both the
// coalesced fill and the fragment loads:
//   As[m][k] stride 36  -> frag bank = (4g + tg) mod 32  (perfect permutation)
//   Bs[k][n] stride 136 -> frag bank = (8tg + g) mod 32  (perfect permutation)
#define TBM 128
#define TBN 128
#define TBK 32
#define ASTR 36
#define BSTR 136

__global__ __launch_bounds__(256) void gemm_tf32(
    const float* __restrict__ A, const float* __restrict__ W,
    const float* __restrict__ bias, float* __restrict__ C,
    int M, int Ncol, int K)
{
    __shared__ float As[TBM][ASTR];   // [m][k]
    __shared__ float Bs[TBK][BSTR];   // [k][n]

    const int tid  = threadIdx.x;
    const int lane = tid & 31;
    const int warp = tid >> 5;
    const int g    = lane >> 2;       // groupID (0..7)
    const int tg   = lane & 3;        // thread-in-group (0..3)
    const int wm   = (warp >> 2) * 64;   // warp M offset: 0 / 64
    const int wn   = (warp & 3) * 32;    // warp N offset: 0/32/64/96
    const int bm   = blockIdx.y * TBM;
    const int bn   = blockIdx.x * TBN;

    float c[4][4][4];
#pragma unroll
    for (int mt = 0; mt < 4; mt++)
#pragma unroll
        for (int nt = 0; nt < 4; nt++)
#pragma unroll
            for (int r = 0; r < 4; r++) c[mt][nt][r] = 0.f;

    for (int k0 = 0; k0 < K; k0 += TBK) {
        // fill A tile: 128x32, coalesced along K
#pragma unroll
        for (int i = 0; i < 16; i++) {
            int idx = tid + i * 256;               // 0..4095
            int m = idx >> 5, kk = idx & 31;
            As[m][kk] = to_tf32(A[(size_t)(bm + m) * K + k0 + kk]);
        }
        // fill B tile: 32x128, coalesced along N
#pragma unroll
        for (int i = 0; i < 16; i++) {
            int idx = tid + i * 256;
            int kk = idx >> 7, n = idx & 127;
            Bs[kk][n] = to_tf32(W[(size_t)(k0 + kk) * Ncol + bn + n]);
        }
        __syncthreads();

#pragma unroll
        for (int ks = 0; ks < 4; ks++) {
            const int kb = ks * 8;
            uint32_t afr[4][4], bfr[4][2];
#pragma unroll
            for (int mt = 0; mt < 4; mt++) {
                int mr = wm + mt * 16 + g;
                afr[mt][0] = __float_as_uint(As[mr    ][kb + tg    ]);
                afr[mt][1] = __float_as_uint(As[mr + 8][kb + tg    ]);
                afr[mt][2] = __float_as_uint(As[mr    ][kb + tg + 4]);
                afr[mt][3] = __float_as_uint(As[mr + 8][kb + tg + 4]);
            }
#pragma unroll
            for (int nt = 0; nt < 4; nt++) {
                int nc = wn + nt * 8 + g;
                bfr[nt][0] = __float_as_uint(Bs[kb + tg    ][nc]);
                bfr[nt][1] = __float_as_uint(Bs[kb + tg + 4][nc]);
            }
#pragma unroll
            for (int mt = 0; mt < 4; mt++)
#pragma unroll
                for (int nt = 0; nt < 4; nt++) {
                    asm volatile(
                        "mma.sync.aligned.m16n8k8.row.col.f32.tf32.tf32.f32 "
                        "{%0,%1,%2,%3}, {%4,%5,%6,%7}, {%8,%9}, {%0,%1,%2,%3};"
                        : "+f"(c[mt][nt][0]), "+f"(c[mt][nt][1]),
                          "+f"(c[mt][nt][2]), "+f"(c[mt][nt][3])
                        : "r"(afr[mt][0]), "r"(afr[mt][1]),
                          "r"(afr[mt][2]), "r"(afr[mt][3]),
                          "r"(bfr[nt][0]), "r"(bfr[nt][1]));
                }
        }
        __syncthreads();
    }

    // epilogue: c0,c1 at (g, 2tg), (g, 2tg+1); c2,c3 at row +8
#pragma unroll
    for (int mt = 0; mt < 4; mt++) {
        int r0 = bm + wm + mt * 16 + g;
#pragma unroll
        for (int nt = 0; nt < 4; nt++) {
            int col = bn + wn + nt * 8 + 2 * tg;
            float b0 = bias ? bias[col] : 0.f;
            float b1 = bias ? bias[col + 1] : 0.f;
            float2 v0 = make_float2(c[mt][nt][0] + b0, c[mt][nt][1] + b1);
            float2 v1 = make_float2(c[mt][nt][2] + b0, c[mt][nt][3] + b1);
            *(float2*)&C[(size_t)r0 * Ncol + col] = v0;
            *(float2*)&C[(size_t)(r0 + 8) * Ncol + col] = v1;
        }
    }
}

// ---------------- misc elementwise kernels ----------------
__global__ void concat_kernel(const float* __restrict__ x_node,
                              const float* __restrict__ x_log)
{
    size_t idx = (size_t)blockIdx.x * blockDim.x + threadIdx.x;   // NN_*256
    if (idx >= (size_t)NN_ * DIN) return;
    int i = (int)(idx >> 8), c = (int)(idx & 255);
    g_node[idx] = (c < 128) ? x_node[(size_t)i * 128 + c]
                            : x_log[(size_t)i * 128 + (c - 128)];
}

__global__ void init_softmax1_kernel() {
    int idx = blockIdx.x * blockDim.x + threadIdx.x;
    if (idx >= NN_ * 4) return;
    g_amax1[idx] = -FLT_MAX;
    g_den1[idx]  = 0.f;
}

__global__ void init_softmax2_kernel() {
    int idx = blockIdx.x * blockDim.x + threadIdx.x;
    if (idx >= E1_ * 4) return;
    g_amax2[idx] = -FLT_MAX;
    g_den2[idx]  = 0.f;
}

__global__ void init_nodeout_kernel(const float* __restrict__ bias) {
    size_t idx = (size_t)blockIdx.x * blockDim.x + threadIdx.x;
    if (idx >= (size_t)NN_ * DIN) return;
    g_nodeout[idx] = bias[idx & 255];
}

// ---------------- layer 1 edge kernels (warp per edge) ----------------
__global__ __launch_bounds__(256) void alpha1_kernel(const int* __restrict__ adj,
                                                     const float* __restrict__ att)
{
    int warp = (blockIdx.x * blockDim.x + threadIdx.x) >> 5;
    int lane = threadIdx.x & 31;
    if (warp >= E1_) return;
    int src = adj[warp], dst = adj[E1_ + warp];
    const float* xl = g_xl + (size_t)src * DIN;
    const float* xr = g_xr + (size_t)dst * DIN;
    const float* ee = g_e1 + (size_t)warp * DIN;
    float p[4];
#pragma unroll
    for (int h = 0; h < 4; h++) {
        p[h] = 0.f;
#pragma unroll
        for (int jj = 0; jj < 2; jj++) {
            int c = h * 64 + jj * 32 + lane;
            float m = lrelu02(xl[c] + xr[c] + ee[c]);
            p[h] += m * att[c];
        }
    }
#pragma unroll
    for (int h = 0; h < 4; h++) {
#pragma unroll
        for (int off = 16; off > 0; off >>= 1)
            p[h] += __shfl_xor_sync(0xffffffff, p[h], off);
    }
    if (lane < 4) {
        g_alpha1[(size_t)warp * 4 + lane] = p[lane];
        atomicMaxFloat(&g_amax1[(size_t)dst * 4 + lane], p[lane]);
    }
}

__global__ void exp1_kernel(const int* __restrict__ adj) {
    int idx = blockIdx.x * blockDim.x + threadIdx.x;
    if (idx >= E1_ * 4) return;
    int e = idx >> 2, h = idx & 3;
    int dst = adj[E1_ + e];
    float ex = expf(g_alpha1[idx] - g_amax1[dst * 4 + h]);
    g_alpha1[idx] = ex;
    atomicAdd(&g_den1[dst * 4 + h], ex);
}

__global__ __launch_bounds__(256) void agg1_kernel(const int* __restrict__ adj) {
    int warp = (blockIdx.x * blockDim.x + threadIdx.x) >> 5;
    int lane = threadIdx.x & 31;
    if (warp >= E1_) return;
    int src = adj[warp], dst = adj[E1_ + warp];
    float a[4];
#pragma unroll
    for (int h = 0; h < 4; h++)
        a[h] = g_alpha1[(size_t)warp * 4 + h] / (g_den1[(size_t)dst * 4 + h] + EPSV);
    const float* xl = g_xl + (size_t)src * DIN;
    float* out = g_nodeout + (size_t)dst * DIN;
#pragma unroll
    for (int h = 0; h < 4; h++) {
#pragma unroll
        for (int jj = 0; jj < 2; jj++) {
            int c = h * 64 + jj * 32 + lane;
            atomicAdd(&out[c], a[h] * xl[c]);
        }
    }
}

// ---------------- layer 2 edge kernels ----------------
__global__ __launch_bounds__(256) void alpha2_kernel(const int* __restrict__ adj,
                                                     const int* __restrict__ efea,
                                                     const float* __restrict__ att)
{
    int warp = (blockIdx.x * blockDim.x + threadIdx.x) >> 5;
    int lane = threadIdx.x & 31;
    if (warp >= E2_) return;
    int src = adj[warp], dst = adj[E2_ + warp];
    int ef = efea[warp];
    const float* xl = g_xl2 + (size_t)src * DED;
    const float* xr = g_xr2 + (size_t)dst * DED;
    const float* ee = g_gfeat + (size_t)ef * DED;
    float p[4];
#pragma unroll
    for (int h = 0; h < 4; h++) {
        int c = h * 32 + lane;
        float m = lrelu02(xl[c] + xr[c] + ee[c]);
        p[h] = m * att[c];
    }
#pragma unroll
    for (int h = 0; h < 4; h++) {
#pragma unroll
        for (int off = 16; off > 0; off >>= 1)
            p[h] += __shfl_xor_sync(0xffffffff, p[h], off);
    }
    if (lane < 4) {
        g_alpha2[(size_t)warp * 4 + lane] = p[lane];
        atomicMaxFloat(&g_amax2[(size_t)dst * 4 + lane], p[lane]);
    }
}

__global__ void exp2_kernel(const int* __restrict__ adj) {
    size_t idx = (size_t)blockIdx.x * blockDim.x + threadIdx.x;
    if (idx >= (size_t)E2_ * 4) return;
    int e = (int)(idx >> 2), h = (int)(idx & 3);
    int dst = adj[E2_ + e];
    float ex = expf(g_alpha2[idx] - g_amax2[(size_t)dst * 4 + h]);
    g_alpha2[idx] = ex;
    atomicAdd(&g_den2[(size_t)dst * 4 + h], ex);
}

// split node_out into xn / xlg regions of d_out and seed xt region with bias2
__global__ void out_split_kernel(float* __restrict__ out, const float* __restrict__ bias2) {
    size_t idx = (size_t)blockIdx.x * blockDim.x + threadIdx.x;
    const size_t XN = (size_t)NN_ * 128;
    const size_t XT = (size_t)E1_ * 128;
    if (idx >= XN + XT + XN) return;
    if (idx < XN) {
        int i = (int)(idx >> 7), c = (int)(idx & 127);
        out[idx] = g_nodeout[(size_t)i * DIN + c];
    } else if (idx < XN + XT) {
        out[idx] = bias2[idx & 127];
    } else {
        size_t r = idx - (XN + XT);
        int i = (int)(r >> 7), c = (int)(r & 127);
        out[idx] = g_nodeout[(size_t)i * DIN + 128 + c];
    }
}

__global__ __launch_bounds__(256) void agg2_kernel(const int* __restrict__ adj,
                                                   float* __restrict__ out_xt)
{
    int warp = (blockIdx.x * blockDim.x + threadIdx.x) >> 5;
    int lane = threadIdx.x & 31;
    if (warp >= E2_) return;
    int src = adj[warp], dst = adj[E2_ + warp];
    float a[4];
#pragma unroll
    for (int h = 0; h < 4; h++)
        a[h] = g_alpha2[(size_t)warp * 4 + h] / (g_den2[(size_t)dst * 4 + h] + EPSV);
    const float* xl = g_xl2 + (size_t)src * DED;
    float* out = out_xt + (size_t)dst * DED;
#pragma unroll
    for (int h = 0; h < 4; h++) {
        int c = h * 32 + lane;
        atomicAdd(&out[c], a[h] * xl[c]);
    }
}

// ---------------- launch ----------------
extern "C" void kernel_launch(void* const* d_in, const int* in_sizes, int n_in,
                              void* d_out, int out_size)
{
    const float* x_node   = (const float*)d_in[0];
    const float* x_trace  = (const float*)d_in[1];
    const float* x_log    = (const float*)d_in[2];
    const int*   node_adj = (const int*)d_in[3];
    const int*   edge_adj = (const int*)d_in[4];
    const int*   edge_efea= (const int*)d_in[5];
    const float* n2n_Wl   = (const float*)d_in[6];
    const float* n2n_bl   = (const float*)d_in[7];
    const float* n2n_Wr   = (const float*)d_in[8];
    const float* n2n_br   = (const float*)d_in[9];
    const float* n2n_We   = (const float*)d_in[10];
    const float* n2n_att  = (const float*)d_in[11];
    const float* n2n_bias = (const float*)d_in[12];
    const float* e2n_Wl   = (const float*)d_in[13];
    const float* e2n_bl   = (const float*)d_in[14];
    const float* e2n_Wr   = (const float*)d_in[15];
    const float* e2n_br   = (const float*)d_in[16];
    const float* e2n_We   = (const float*)d_in[17];
    const float* e2n_att  = (const float*)d_in[18];
    const float* e2n_bias = (const float*)d_in[19];
    float* out = (float*)d_out;

    float* p_node;    cudaGetSymbolAddress((void**)&p_node,    g_node);
    float* p_xl;      cudaGetSymbolAddress((void**)&p_xl,      g_xl);
    float* p_xr;      cudaGetSymbolAddress((void**)&p_xr,      g_xr);
    float* p_e1;      cudaGetSymbolAddress((void**)&p_e1,      g_e1);
    float* p_nodeout; cudaGetSymbolAddress((void**)&p_nodeout, g_nodeout);
    float* p_xl2;     cudaGetSymbolAddress((void**)&p_xl2,     g_xl2);
    float* p_xr2;     cudaGetSymbolAddress((void**)&p_xr2,     g_xr2);
    float* p_g;       cudaGetSymbolAddress((void**)&p_g,       g_gfeat);

    // ---- prep ----
    concat_kernel<<<(NN_ * DIN) / 256, 256>>>(x_node, x_log);
    init_softmax1_kernel<<<(NN_ * 4) / 256, 256>>>();
    init_softmax2_kernel<<<(E1_ * 4) / 256, 256>>>();
    init_nodeout_kernel<<<(NN_ * DIN) / 256, 256>>>(n2n_bias);

    // ---- layer-1 GEMMs (tf32 tensor cores) ----
    {
        dim3 g1(DIN / TBN, NN_ / TBM);
        gemm_tf32<<<g1, 256>>>(p_node, n2n_Wl, n2n_bl, p_xl, NN_, DIN, DIN);
        gemm_tf32<<<g1, 256>>>(p_node, n2n_Wr, n2n_br, p_xr, NN_, DIN, DIN);
        dim3 ge(DIN / TBN, E1_ / TBM);
        gemm_tf32<<<ge, 256>>>(x_trace, n2n_We, nullptr, p_e1, E1_, DIN, 128);
        // layer-2 source/target transforms depend only on trace
        dim3 g2(DED / TBN, E1_ / TBM);
        gemm_tf32<<<g2, 256>>>(x_trace, e2n_Wl, e2n_bl, p_xl2, E1_, DED, DED);
        gemm_tf32<<<g2, 256>>>(x_trace, e2n_Wr, e2n_br, p_xr2, E1_, DED, DED);
    }

    // ---- layer-1 attention + softmax + aggregate ----
    alpha1_kernel<<<E1_ / 8, 256>>>(node_adj, n2n_att);
    exp1_kernel<<<(E1_ * 4) / 256, 256>>>(node_adj);
    agg1_kernel<<<E1_ / 8, 256>>>(node_adj);

    // ---- layer-2: edge attr = node_out[efea] @ We2 == gather of g = node_out @ We2 ----
    {
        dim3 gg(DED / TBN, NN_ / TBM);
        gemm_tf32<<<gg, 256>>>(p_nodeout, e2n_We, nullptr, p_g, NN_, DED, DIN);
    }

    alpha2_kernel<<<E2_ / 8, 256>>>(edge_adj, edge_efea, e2n_att);
    exp2_kernel<<<(E2_ * 4) / 256, 256>>>(edge_adj);

    {
        size_t total = (size_t)NN_ * 128 * 2 + (size_t)E1_ * 128;
        out_split_kernel<<<(unsigned)((total + 255) / 256), 256>>>(out, e2n_bias);
    }
    agg2_kernel<<<E2_ / 8, 256>>>(edge_adj, out + (size_t)NN_ * 128);
}

// round 4
// speedup vs baseline: 1.8576x; 1.3571x over previous
#include <cuda_runtime.h>
#include <stdint.h>
#include <math.h>
#include <float.h>

// ---------------- problem constants ----------------
#define NN_   8192      // nodes
#define E1_   131072    // node-graph edges (= trace rows)
#define E2_   524288    // line-graph edges
#define DIN   256       // layer1 channels (4 heads x 64)
#define DED   128       // layer2 channels (4 heads x 32)
#define EPSV  1e-16f

// ---------------- scratch (static device, no allocs) ----------------
__device__ float g_node   [(size_t)NN_ * DIN];
__device__ float g_xl     [(size_t)NN_ * DIN];
__device__ float g_xr     [(size_t)NN_ * DIN];
__device__ float g_alpha1 [(size_t)E1_ * 4];
__device__ float g_amax1  [(size_t)NN_ * 4];
__device__ float g_den1   [(size_t)NN_ * 4];
__device__ float g_nodeout[(size_t)NN_ * DIN];
__device__ float g_xl2    [(size_t)E1_ * DED];
__device__ float g_xr2    [(size_t)E1_ * DED];
__device__ float g_gfeat  [(size_t)NN_ * DED];
__device__ float g_alpha2 [(size_t)E2_ * 4];
__device__ float g_amax2  [(size_t)E1_ * 4];
__device__ float g_den2   [(size_t)E1_ * 4];

// ---------------- helpers ----------------
__device__ __forceinline__ void atomicMaxFloat(float* addr, float val) {
    if (val >= 0.f) atomicMax((int*)addr, __float_as_int(val));
    else            atomicMin((unsigned int*)addr, __float_as_uint(val));
}
__device__ __forceinline__ float lrelu02(float x) { return x > 0.f ? x : 0.2f * x; }
__device__ __forceinline__ uint32_t to_tf32(float v) {
    uint32_t t;
    asm("cvt.rna.tf32.f32 %0, %1;" : "=r"(t) : "f"(v));
    return t;
}
__device__ __forceinline__ void cp16(uint32_t dst, const void* src) {
    asm volatile("cp.async.cg.shared.global [%0], [%1], 16;" :: "r"(dst), "l"(src));
}

// ---------------- tf32 GEMM tiles ----------------
#define TBM 128
#define TBN 128
#define TBK 32
#define STG 8960                 // floats per stage: 128*36 + 32*136
#define AS(S,M,K_) smem[(S)*STG + (M)*36 + (K_)]
#define BS(S,KK,N_) smem[(S)*STG + 4608 + (KK)*136 + (N_)]
#define ET(R,C) smem[(R)*132 + (C)]

struct Frag { float c[4][4][4]; };

__device__ __forceinline__ void load_stage(float* smem, int s,
    const float* __restrict__ A, const float* __restrict__ W,
    int bm, int bn, int k0, int K, int Ncol, int tid)
{
#pragma unroll
    for (int i = 0; i < 4; i++) {
        int idx = tid + i * 256;
        int m = idx >> 3, kc = idx & 7;
        cp16((uint32_t)__cvta_generic_to_shared(&AS(s, m, kc * 4)),
             &A[(size_t)(bm + m) * K + k0 + kc * 4]);
    }
#pragma unroll
    for (int i = 0; i < 4; i++) {
        int idx = tid + i * 256;
        int kk = idx >> 5, nc = idx & 31;
        cp16((uint32_t)__cvta_generic_to_shared(&BS(s, kk, nc * 4)),
             &W[(size_t)(k0 + kk) * Ncol + bn + nc * 4]);
    }
    asm volatile("cp.async.commit_group;");
}

__device__ __forceinline__ void compute_stage(const float* smem, int s, Frag& f,
                                              int wm, int wn, int g, int tg)
{
#pragma unroll
    for (int ks = 0; ks < 4; ks++) {
        const int kb = ks * 8;
        uint32_t afr[4][4], bfr[4][2];
#pragma unroll
        for (int mt = 0; mt < 4; mt++) {
            int mr = wm + mt * 16 + g;
            afr[mt][0] = to_tf32(AS(s, mr,     kb + tg));
            afr[mt][1] = to_tf32(AS(s, mr + 8, kb + tg));
            afr[mt][2] = to_tf32(AS(s, mr,     kb + tg + 4));
            afr[mt][3] = to_tf32(AS(s, mr + 8, kb + tg + 4));
        }
#pragma unroll
        for (int nt = 0; nt < 4; nt++) {
            int nc = wn + nt * 8 + g;
            bfr[nt][0] = to_tf32(BS(s, kb + tg,     nc));
            bfr[nt][1] = to_tf32(BS(s, kb + tg + 4, nc));
        }
#pragma unroll
        for (int mt = 0; mt < 4; mt++)
#pragma unroll
            for (int nt = 0; nt < 4; nt++) {
                asm volatile(
                    "mma.sync.aligned.m16n8k8.row.col.f32.tf32.tf32.f32 "
                    "{%0,%1,%2,%3}, {%4,%5,%6,%7}, {%8,%9}, {%0,%1,%2,%3};"
                    : "+f"(f.c[mt][nt][0]), "+f"(f.c[mt][nt][1]),
                      "+f"(f.c[mt][nt][2]), "+f"(f.c[mt][nt][3])
                    : "r"(afr[mt][0]), "r"(afr[mt][1]),
                      "r"(afr[mt][2]), "r"(afr[mt][3]),
                      "r"(bfr[nt][0]), "r"(bfr[nt][1]));
            }
    }
}

// Pipelined GEMM, optionally dual-output (blockIdx.z selects W/bias/C).
__global__ __launch_bounds__(256) void gemm_pipe(
    const float* __restrict__ A,
    const float* __restrict__ W0, const float* __restrict__ W1,
    const float* __restrict__ b0, const float* __restrict__ b1,
    float* __restrict__ C0, float* __restrict__ C1,
    int M, int Ncol, int K)
{
    extern __shared__ float smem[];
    const int tid  = threadIdx.x;
    const int lane = tid & 31, warp = tid >> 5;
    const int g = lane >> 2, tg = lane & 3;
    const int wm = (warp >> 2) * 64, wn = (warp & 3) * 32;
    const int bm = blockIdx.y * TBM, bn = blockIdx.x * TBN;
    const int z  = blockIdx.z;
    const float* W    = z ? W1 : W0;
    const float* bias = z ? b1 : b0;
    float* C          = z ? C1 : C0;

    Frag f;
#pragma unroll
    for (int mt = 0; mt < 4; mt++)
#pragma unroll
        for (int nt = 0; nt < 4; nt++)
#pragma unroll
            for (int r = 0; r < 4; r++) f.c[mt][nt][r] = 0.f;

    const int KT = K / TBK;
    load_stage(smem, 0, A, W, bm, bn, 0, K, Ncol, tid);
    for (int kt = 0; kt < KT; kt++) {
        int s = kt & 1;
        if (kt + 1 < KT) {
            load_stage(smem, s ^ 1, A, W, bm, bn, (kt + 1) * TBK, K, Ncol, tid);
            asm volatile("cp.async.wait_group 1;");
        } else {
            asm volatile("cp.async.wait_group 0;");
        }
        __syncthreads();
        compute_stage(smem, s, f, wm, wn, g, tg);
        __syncthreads();
    }

#pragma unroll
    for (int mt = 0; mt < 4; mt++) {
        int r0 = bm + wm + mt * 16 + g;
#pragma unroll
        for (int nt = 0; nt < 4; nt++) {
            int col = bn + wn + nt * 8 + 2 * tg;
            float bb0 = bias ? bias[col] : 0.f;
            float bb1 = bias ? bias[col + 1] : 0.f;
            float2 v0 = make_float2(f.c[mt][nt][0] + bb0, f.c[mt][nt][1] + bb1);
            float2 v1 = make_float2(f.c[mt][nt][2] + bb0, f.c[mt][nt][3] + bb1);
            *(float2*)&C[(size_t)r0 * Ncol + col] = v0;
            *(float2*)&C[(size_t)(r0 + 8) * Ncol + col] = v1;
        }
    }
}

// Fused: e1 = trace @ We (no bias), kept in smem, then alpha1 = att . lrelu(xl[src]+xr[dst]+e1)
// grid (2, E1/128): blockIdx.x selects channels [0,128) = heads {0,1} or [128,256) = heads {2,3}.
__global__ __launch_bounds__(256) void gemm_alpha1_fused(
    const float* __restrict__ A,      // x_trace [E1,128]
    const float* __restrict__ W,      // n2n_We [128,256]
    const int*   __restrict__ adj,    // node_adj [2,E1]
    const float* __restrict__ att)    // [4,64]
{
    extern __shared__ float smem[];
    const int tid  = threadIdx.x;
    const int lane = tid & 31, warp = tid >> 5;
    const int g = lane >> 2, tg = lane & 3;
    const int wm = (warp >> 2) * 64, wn = (warp & 3) * 32;
    const int bm = blockIdx.y * TBM, bn = blockIdx.x * TBN;
    const int K = 128, Ncol = DIN;

    Frag f;
#pragma unroll
    for (int mt = 0; mt < 4; mt++)
#pragma unroll
        for (int nt = 0; nt < 4; nt++)
#pragma unroll
            for (int r = 0; r < 4; r++) f.c[mt][nt][r] = 0.f;

    for (int kt = 0; kt < K / TBK; kt++) {
        load_stage(smem, 0, A, W, bm, bn, kt * TBK, K, Ncol, tid);
        asm volatile("cp.async.wait_group 0;");
        __syncthreads();
        compute_stage(smem, 0, f, wm, wn, g, tg);
        __syncthreads();
    }

    // stage e1 tile into smem (overwrites A/B buffers; synced above)
#pragma unroll
    for (int mt = 0; mt < 4; mt++) {
        int r0 = wm + mt * 16 + g;
#pragma unroll
        for (int nt = 0; nt < 4; nt++) {
            int col = wn + nt * 8 + 2 * tg;
            ET(r0, col)         = f.c[mt][nt][0];
            ET(r0, col + 1)     = f.c[mt][nt][1];
            ET(r0 + 8, col)     = f.c[mt][nt][2];
            ET(r0 + 8, col + 1) = f.c[mt][nt][3];
        }
    }
    __syncthreads();

    // phase 2: per-edge attention logits for this head-pair
    const float4 av = *(const float4*)&att[bn + lane * 4];
#pragma unroll 2
    for (int er = warp * 16; er < warp * 16 + 16; er++) {
        int e = bm + er;
        int src = adj[e], dst = adj[E1_ + e];
        float4 xlv = *(const float4*)&g_xl[(size_t)src * DIN + bn + lane * 4];
        float4 xrv = *(const float4*)&g_xr[(size_t)dst * DIN + bn + lane * 4];
        float p;
        p  = lrelu02(xlv.x + xrv.x + ET(er, lane * 4 + 0)) * av.x;
        p += lrelu02(xlv.y + xrv.y + ET(er, lane * 4 + 1)) * av.y;
        p += lrelu02(xlv.z + xrv.z + ET(er, lane * 4 + 2)) * av.z;
        p += lrelu02(xlv.w + xrv.w + ET(er, lane * 4 + 3)) * av.w;
#pragma unroll
        for (int off = 8; off > 0; off >>= 1)
            p += __shfl_xor_sync(0xffffffff, p, off);
        if (lane == 0 || lane == 16) {
            int head = 2 * blockIdx.x + (lane >> 4);
            g_alpha1[(size_t)e * 4 + head] = p;
            atomicMaxFloat(&g_amax1[(size_t)dst * 4 + head], p);
        }
    }
}

// ---------------- prep: concat + all inits ----------------
__global__ void prep_kernel(const float* __restrict__ x_node,
                            const float* __restrict__ x_log,
                            const float* __restrict__ bias1)
{
    size_t idx = (size_t)blockIdx.x * blockDim.x + threadIdx.x;   // NN_*256 = 2M
    if (idx >= (size_t)NN_ * DIN) return;
    int i = (int)(idx >> 8), c = (int)(idx & 255);
    g_node[idx] = (c < 128) ? x_node[(size_t)i * 128 + c]
                            : x_log[(size_t)i * 128 + (c - 128)];
    g_nodeout[idx] = bias1[c];
    if (idx < NN_ * 4) { g_amax1[idx] = -FLT_MAX; g_den1[idx] = 0.f; }
    if (idx < (size_t)E1_ * 4) { g_amax2[idx] = -FLT_MAX; g_den2[idx] = 0.f; }
}

// ---------------- layer-1 softmax + aggregate ----------------
__global__ void exp1_kernel(const int* __restrict__ adj) {
    int idx = blockIdx.x * blockDim.x + threadIdx.x;
    if (idx >= E1_ * 4) return;
    int e = idx >> 2, h = idx & 3;
    int dst = adj[E1_ + e];
    float ex = expf(g_alpha1[idx] - g_amax1[dst * 4 + h]);
    g_alpha1[idx] = ex;
    atomicAdd(&g_den1[dst * 4 + h], ex);
}

__global__ __launch_bounds__(256) void agg1_kernel(const int* __restrict__ adj) {
    int warp = (blockIdx.x * blockDim.x + threadIdx.x) >> 5;
    int lane = threadIdx.x & 31;
    if (warp >= E1_) return;
    int src = adj[warp], dst = adj[E1_ + warp];
    float a[4];
#pragma unroll
    for (int h = 0; h < 4; h++)
        a[h] = g_alpha1[(size_t)warp * 4 + h] / (g_den1[(size_t)dst * 4 + h] + EPSV);
    const float* xl = g_xl + (size_t)src * DIN;
    float* out = g_nodeout + (size_t)dst * DIN;
#pragma unroll
    for (int h = 0; h < 4; h++) {
#pragma unroll
        for (int jj = 0; jj < 2; jj++) {
            int c = h * 64 + jj * 32 + lane;
            atomicAdd(&out[c], a[h] * xl[c]);
        }
    }
}

// ---------------- layer-2 edge kernels ----------------
__global__ __launch_bounds__(256) void alpha2_kernel(const int* __restrict__ adj,
                                                     const int* __restrict__ efea,
                                                     const float* __restrict__ att)
{
    int warp = (blockIdx.x * blockDim.x + threadIdx.x) >> 5;
    int lane = threadIdx.x & 31;
    if (warp >= E2_) return;
    int src = adj[warp], dst = adj[E2_ + warp];
    int ef = efea[warp];
    const float* xl = g_xl2 + (size_t)src * DED;
    const float* xr = g_xr2 + (size_t)dst * DED;
    const float* ee = g_gfeat + (size_t)ef * DED;
    float p[4];
#pragma unroll
    for (int h = 0; h < 4; h++) {
        int c = h * 32 + lane;
        float m = lrelu02(xl[c] + xr[c] + ee[c]);
        p[h] = m * att[c];
    }
#pragma unroll
    for (int h = 0; h < 4; h++) {
#pragma unroll
        for (int off = 16; off > 0; off >>= 1)
            p[h] += __shfl_xor_sync(0xffffffff, p[h], off);
    }
    if (lane < 4) {
        g_alpha2[(size_t)warp * 4 + lane] = p[lane];
        atomicMaxFloat(&g_amax2[(size_t)dst * 4 + lane], p[lane]);
    }
}

__global__ void exp2_kernel(const int* __restrict__ adj) {
    size_t idx = (size_t)blockIdx.x * blockDim.x + threadIdx.x;
    if (idx >= (size_t)E2_ * 4) return;
    int e = (int)(idx >> 2), h = (int)(idx & 3);
    int dst = adj[E2_ + e];
    float ex = expf(g_alpha2[idx] - g_amax2[(size_t)dst * 4 + h]);
    g_alpha2[idx] = ex;
    atomicAdd(&g_den2[(size_t)dst * 4 + h], ex);
}

__global__ void out_split_kernel(float* __restrict__ out, const float* __restrict__ bias2) {
    size_t idx = (size_t)blockIdx.x * blockDim.x + threadIdx.x;
    const size_t XN = (size_t)NN_ * 128;
    const size_t XT = (size_t)E1_ * 128;
    if (idx >= XN + XT + XN) return;
    if (idx < XN) {
        int i = (int)(idx >> 7), c = (int)(idx & 127);
        out[idx] = g_nodeout[(size_t)i * DIN + c];
    } else if (idx < XN + XT) {
        out[idx] = bias2[idx & 127];
    } else {
        size_t r = idx - (XN + XT);
        int i = (int)(r >> 7), c = (int)(r & 127);
        out[idx] = g_nodeout[(size_t)i * DIN + 128 + c];
    }
}

__global__ __launch_bounds__(256) void agg2_kernel(const int* __restrict__ adj,
                                                   float* __restrict__ out_xt)
{
    int warp = (blockIdx.x * blockDim.x + threadIdx.x) >> 5;
    int lane = threadIdx.x & 31;
    if (warp >= E2_) return;
    int src = adj[warp], dst = adj[E2_ + warp];
    float a[4];
#pragma unroll
    for (int h = 0; h < 4; h++)
        a[h] = g_alpha2[(size_t)warp * 4 + h] / (g_den2[(size_t)dst * 4 + h] + EPSV);
    const float* xl = g_xl2 + (size_t)src * DED;
    float* out = out_xt + (size_t)dst * DED;
#pragma unroll
    for (int h = 0; h < 4; h++) {
        int c = h * 32 + lane;
        atomicAdd(&out[c], a[h] * xl[c]);
    }
}

// ---------------- launch ----------------
extern "C" void kernel_launch(void* const* d_in, const int* in_sizes, int n_in,
                              void* d_out, int out_size)
{
    const float* x_node   = (const float*)d_in[0];
    const float* x_trace  = (const float*)d_in[1];
    const float* x_log    = (const float*)d_in[2];
    const int*   node_adj = (const int*)d_in[3];
    const int*   edge_adj = (const int*)d_in[4];
    const int*   edge_efea= (const int*)d_in[5];
    const float* n2n_Wl   = (const float*)d_in[6];
    const float* n2n_bl   = (const float*)d_in[7];
    const float* n2n_Wr   = (const float*)d_in[8];
    const float* n2n_br   = (const float*)d_in[9];
    const float* n2n_We   = (const float*)d_in[10];
    const float* n2n_att  = (const float*)d_in[11];
    const float* n2n_bias = (const float*)d_in[12];
    const float* e2n_Wl   = (const float*)d_in[13];
    const float* e2n_bl   = (const float*)d_in[14];
    const float* e2n_Wr   = (const float*)d_in[15];
    const float* e2n_br   = (const float*)d_in[16];
    const float* e2n_We   = (const float*)d_in[17];
    const float* e2n_att  = (const float*)d_in[18];
    const float* e2n_bias = (const float*)d_in[19];
    float* out = (float*)d_out;

    float* p_node;    cudaGetSymbolAddress((void**)&p_node,    g_node);
    float* p_xl;      cudaGetSymbolAddress((void**)&p_xl,      g_xl);
    float* p_xr;      cudaGetSymbolAddress((void**)&p_xr,      g_xr);
    float* p_nodeout; cudaGetSymbolAddress((void**)&p_nodeout, g_nodeout);
    float* p_xl2;     cudaGetSymbolAddress((void**)&p_xl2,     g_xl2);
    float* p_xr2;     cudaGetSymbolAddress((void**)&p_xr2,     g_xr2);
    float* p_g;       cudaGetSymbolAddress((void**)&p_g,       g_gfeat);

    const int SMEM_PIPE  = 2 * STG * 4;          // 71680
    const int SMEM_FUSED = 128 * 132 * 4;        // 67584
    static int attr_done = 0;
    if (!attr_done) {
        cudaFuncSetAttribute(gemm_pipe, cudaFuncAttributeMaxDynamicSharedMemorySize, SMEM_PIPE);
        cudaFuncSetAttribute(gemm_alpha1_fused, cudaFuncAttributeMaxDynamicSharedMemorySize, SMEM_FUSED);
        attr_done = 1;
    }

    // 1: prep (concat + softmax inits + nodeout=bias)
    prep_kernel<<<(NN_ * DIN) / 256, 256>>>(x_node, x_log, n2n_bias);

    // 2: xl/xr dual GEMM
    {
        dim3 gdim(DIN / TBN, NN_ / TBM, 2);
        gemm_pipe<<<gdim, 256, SMEM_PIPE>>>(p_node, n2n_Wl, n2n_Wr, n2n_bl, n2n_br,
                                            p_xl, p_xr, NN_, DIN, DIN);
    }
    // 3: xl2/xr2 dual GEMM (depends only on x_trace)
    {
        dim3 gdim(DED / TBN, E1_ / TBM, 2);
        gemm_pipe<<<gdim, 256, SMEM_PIPE>>>(x_trace, e2n_Wl, e2n_Wr, e2n_bl, e2n_br,
                                            p_xl2, p_xr2, E1_, DED, DED);
    }
    // 4: fused e1 GEMM + alpha1
    {
        dim3 gdim(DIN / TBN, E1_ / TBM);
        gemm_alpha1_fused<<<gdim, 256, SMEM_FUSED>>>(x_trace, n2n_We, node_adj, n2n_att);
    }
    // 5-6: layer-1 softmax + aggregate
    exp1_kernel<<<(E1_ * 4) / 256, 256>>>(node_adj);
    agg1_kernel<<<E1_ / 8, 256>>>(node_adj);

    // 7: gfeat = node_out @ We2
    {
        dim3 gdim(DED / TBN, NN_ / TBM, 1);
        gemm_pipe<<<gdim, 256, SMEM_PIPE>>>(p_nodeout, e2n_We, e2n_We, nullptr, nullptr,
                                            p_g, p_g, NN_, DED, DIN);
    }
    // 8-9: layer-2 attention + softmax
    alpha2_kernel<<<E2_ / 8, 256>>>(edge_adj, edge_efea, e2n_att);
    exp2_kernel<<<(E2_ * 4) / 256, 256>>>(edge_adj);

    // 10-11: outputs
    {
        size_t total = (size_t)NN_ * 128 * 2 + (size_t)E1_ * 128;
        out_split_kernel<<<(unsigned)((total + 255) / 256), 256>>>(out, e2n_bias);
    }
    agg2_kernel<<<E2_ / 8, 256>>>(edge_adj, out + (size_t)NN_ * 128);
}

// round 5
// speedup vs baseline: 1.9421x; 1.0455x over previous
#include <cuda_runtime.h>
#include <stdint.h>
#include <math.h>
#include <float.h>

// ---------------- problem constants ----------------
#define NN_   8192      // nodes
#define E1_   131072    // node-graph edges (= trace rows)
#define E2_   524288    // line-graph edges
#define DIN   256       // layer1 channels (4 heads x 64)
#define DED   128       // layer2 channels (4 heads x 32)
#define EPSV  1e-16f

// ---------------- scratch (static device, no allocs) ----------------
__device__ float g_node   [(size_t)NN_ * DIN];
__device__ float g_xl     [(size_t)NN_ * DIN];
__device__ float g_xr     [(size_t)NN_ * DIN];
__device__ float g_alpha1 [(size_t)E1_ * 4];
__device__ float g_amax1  [(size_t)NN_ * 4];
__device__ float g_den1   [(size_t)NN_ * 4];
__device__ float g_nodeout[(size_t)NN_ * DIN];
__device__ float g_xl2    [(size_t)E1_ * DED];
__device__ float g_xr2    [(size_t)E1_ * DED];
__device__ float g_gfeat  [(size_t)NN_ * DED];
__device__ float g_alpha2 [(size_t)E2_ * 4];
__device__ float g_amax2  [(size_t)E1_ * 4];
__device__ float g_den2   [(size_t)E1_ * 4];

// ---------------- helpers ----------------
__device__ __forceinline__ void atomicMaxFloat(float* addr, float val) {
    if (val >= 0.f) atomicMax((int*)addr, __float_as_int(val));
    else            atomicMin((unsigned int*)addr, __float_as_uint(val));
}
__device__ __forceinline__ float lrelu02(float x) { return x > 0.f ? x : 0.2f * x; }
__device__ __forceinline__ uint32_t to_tf32(float v) {
    uint32_t t;
    asm("cvt.rna.tf32.f32 %0, %1;" : "=r"(t) : "f"(v));
    return t;
}
__device__ __forceinline__ void cp16(uint32_t dst, const void* src) {
    asm volatile("cp.async.cg.shared.global [%0], [%1], 16;" :: "r"(dst), "l"(src));
}
__device__ __forceinline__ void red_add_v4(float* addr, float4 v) {
    asm volatile("red.global.add.v4.f32 [%0], {%1,%2,%3,%4};"
                 :: "l"(addr), "f"(v.x), "f"(v.y), "f"(v.z), "f"(v.w) : "memory");
}

// ---------------- tf32 GEMM tiles ----------------
#define TBM 128
#define TBN 128
#define TBK 32
#define STG 8960                 // floats per stage: 128*36 + 32*136
#define AS(S,M,K_) smem[(S)*STG + (M)*36 + (K_)]
#define BS(S,KK,N_) smem[(S)*STG + 4608 + (KK)*136 + (N_)]
#define ET(R,C) smem[(R)*132 + (C)]

struct Frag { float c[4][4][4]; };

__device__ __forceinline__ void load_stage(float* smem, int s,
    const float* __restrict__ A, const float* __restrict__ W,
    int bm, int bn, int k0, int K, int Ncol, int tid)
{
#pragma unroll
    for (int i = 0; i < 4; i++) {
        int idx = tid + i * 256;
        int m = idx >> 3, kc = idx & 7;
        cp16((uint32_t)__cvta_generic_to_shared(&AS(s, m, kc * 4)),
             &A[(size_t)(bm + m) * K + k0 + kc * 4]);
    }
#pragma unroll
    for (int i = 0; i < 4; i++) {
        int idx = tid + i * 256;
        int kk = idx >> 5, nc = idx & 31;
        cp16((uint32_t)__cvta_generic_to_shared(&BS(s, kk, nc * 4)),
             &W[(size_t)(k0 + kk) * Ncol + bn + nc * 4]);
    }
    asm volatile("cp.async.commit_group;");
}

__device__ __forceinline__ void compute_stage(const float* smem, int s, Frag& f,
                                              int wm, int wn, int g, int tg)
{
#pragma unroll
    for (int ks = 0; ks < 4; ks++) {
        const int kb = ks * 8;
        uint32_t afr[4][4], bfr[4][2];
#pragma unroll
        for (int mt = 0; mt < 4; mt++) {
            int mr = wm + mt * 16 + g;
            afr[mt][0] = to_tf32(AS(s, mr,     kb + tg));
            afr[mt][1] = to_tf32(AS(s, mr + 8, kb + tg));
            afr[mt][2] = to_tf32(AS(s, mr,     kb + tg + 4));
            afr[mt][3] = to_tf32(AS(s, mr + 8, kb + tg + 4));
        }
#pragma unroll
        for (int nt = 0; nt < 4; nt++) {
            int nc = wn + nt * 8 + g;
            bfr[nt][0] = to_tf32(BS(s, kb + tg,     nc));
            bfr[nt][1] = to_tf32(BS(s, kb + tg + 4, nc));
        }
#pragma unroll
        for (int mt = 0; mt < 4; mt++)
#pragma unroll
            for (int nt = 0; nt < 4; nt++) {
                asm volatile(
                    "mma.sync.aligned.m16n8k8.row.col.f32.tf32.tf32.f32 "
                    "{%0,%1,%2,%3}, {%4,%5,%6,%7}, {%8,%9}, {%0,%1,%2,%3};"
                    : "+f"(f.c[mt][nt][0]), "+f"(f.c[mt][nt][1]),
                      "+f"(f.c[mt][nt][2]), "+f"(f.c[mt][nt][3])
                    : "r"(afr[mt][0]), "r"(afr[mt][1]),
                      "r"(afr[mt][2]), "r"(afr[mt][3]),
                      "r"(bfr[nt][0]), "r"(bfr[nt][1]));
            }
    }
}

// Pipelined GEMM, optionally dual-output (blockIdx.z selects W/bias/C).
__global__ __launch_bounds__(256) void gemm_pipe(
    const float* __restrict__ A,
    const float* __restrict__ W0, const float* __restrict__ W1,
    const float* __restrict__ b0, const float* __restrict__ b1,
    float* __restrict__ C0, float* __restrict__ C1,
    int M, int Ncol, int K)
{
    extern __shared__ float smem[];
    const int tid  = threadIdx.x;
    const int lane = tid & 31, warp = tid >> 5;
    const int g = lane >> 2, tg = lane & 3;
    const int wm = (warp >> 2) * 64, wn = (warp & 3) * 32;
    const int bm = blockIdx.y * TBM, bn = blockIdx.x * TBN;
    const int z  = blockIdx.z;
    const float* W    = z ? W1 : W0;
    const float* bias = z ? b1 : b0;
    float* C          = z ? C1 : C0;

    Frag f;
#pragma unroll
    for (int mt = 0; mt < 4; mt++)
#pragma unroll
        for (int nt = 0; nt < 4; nt++)
#pragma unroll
            for (int r = 0; r < 4; r++) f.c[mt][nt][r] = 0.f;

    const int KT = K / TBK;
    load_stage(smem, 0, A, W, bm, bn, 0, K, Ncol, tid);
    for (int kt = 0; kt < KT; kt++) {
        int s = kt & 1;
        if (kt + 1 < KT) {
            load_stage(smem, s ^ 1, A, W, bm, bn, (kt + 1) * TBK, K, Ncol, tid);
            asm volatile("cp.async.wait_group 1;");
        } else {
            asm volatile("cp.async.wait_group 0;");
        }
        __syncthreads();
        compute_stage(smem, s, f, wm, wn, g, tg);
        __syncthreads();
    }

#pragma unroll
    for (int mt = 0; mt < 4; mt++) {
        int r0 = bm + wm + mt * 16 + g;
#pragma unroll
        for (int nt = 0; nt < 4; nt++) {
            int col = bn + wn + nt * 8 + 2 * tg;
            float bb0 = bias ? bias[col] : 0.f;
            float bb1 = bias ? bias[col + 1] : 0.f;
            float2 v0 = make_float2(f.c[mt][nt][0] + bb0, f.c[mt][nt][1] + bb1);
            float2 v1 = make_float2(f.c[mt][nt][2] + bb0, f.c[mt][nt][3] + bb1);
            *(float2*)&C[(size_t)r0 * Ncol + col] = v0;
            *(float2*)&C[(size_t)(r0 + 8) * Ncol + col] = v1;
        }
    }
}

// Fused: e1 = trace @ We, kept in smem, then alpha1 = att . lrelu(xl[src]+xr[dst]+e1)
// grid (2, E1/128): blockIdx.x selects channels [0,128) = heads {0,1} or [128,256) = heads {2,3}.
__global__ __launch_bounds__(256) void gemm_alpha1_fused(
    const float* __restrict__ A,      // x_trace [E1,128]
    const float* __restrict__ W,      // n2n_We [128,256]
    const int*   __restrict__ adj,    // node_adj [2,E1]
    const float* __restrict__ att)    // [4,64]
{
    extern __shared__ float smem[];
    const int tid  = threadIdx.x;
    const int lane = tid & 31, warp = tid >> 5;
    const int g = lane >> 2, tg = lane & 3;
    const int wm = (warp >> 2) * 64, wn = (warp & 3) * 32;
    const int bm = blockIdx.y * TBM, bn = blockIdx.x * TBN;
    const int K = 128, Ncol = DIN;

    Frag f;
#pragma unroll
    for (int mt = 0; mt < 4; mt++)
#pragma unroll
        for (int nt = 0; nt < 4; nt++)
#pragma unroll
            for (int r = 0; r < 4; r++) f.c[mt][nt][r] = 0.f;

    const int KT = K / TBK;
    load_stage(smem, 0, A, W, bm, bn, 0, K, Ncol, tid);
    for (int kt = 0; kt < KT; kt++) {
        int s = kt & 1;
        if (kt + 1 < KT) {
            load_stage(smem, s ^ 1, A, W, bm, bn, (kt + 1) * TBK, K, Ncol, tid);
            asm volatile("cp.async.wait_group 1;");
        } else {
            asm volatile("cp.async.wait_group 0;");
        }
        __syncthreads();
        compute_stage(smem, s, f, wm, wn, g, tg);
        __syncthreads();
    }

    // stage e1 tile into smem (overwrites stage buffers; synced above)
#pragma unroll
    for (int mt = 0; mt < 4; mt++) {
        int r0 = wm + mt * 16 + g;
#pragma unroll
        for (int nt = 0; nt < 4; nt++) {
            int col = wn + nt * 8 + 2 * tg;
            ET(r0, col)         = f.c[mt][nt][0];
            ET(r0, col + 1)     = f.c[mt][nt][1];
            ET(r0 + 8, col)     = f.c[mt][nt][2];
            ET(r0 + 8, col + 1) = f.c[mt][nt][3];
        }
    }
    __syncthreads();

    // phase 2: per-edge attention logits for this head-pair
    const float4 av = *(const float4*)&att[bn + lane * 4];
#pragma unroll 2
    for (int er = warp * 16; er < warp * 16 + 16; er++) {
        int e = bm + er;
        int src = adj[e], dst = adj[E1_ + e];
        float4 xlv = *(const float4*)&g_xl[(size_t)src * DIN + bn + lane * 4];
        float4 xrv = *(const float4*)&g_xr[(size_t)dst * DIN + bn + lane * 4];
        float p;
        p  = lrelu02(xlv.x + xrv.x + ET(er, lane * 4 + 0)) * av.x;
        p += lrelu02(xlv.y + xrv.y + ET(er, lane * 4 + 1)) * av.y;
        p += lrelu02(xlv.z + xrv.z + ET(er, lane * 4 + 2)) * av.z;
        p += lrelu02(xlv.w + xrv.w + ET(er, lane * 4 + 3)) * av.w;
#pragma unroll
        for (int off = 8; off > 0; off >>= 1)
            p += __shfl_xor_sync(0xffffffff, p, off);
        if (lane == 0 || lane == 16) {
            int head = 2 * blockIdx.x + (lane >> 4);
            g_alpha1[(size_t)e * 4 + head] = p;
            atomicMaxFloat(&g_amax1[(size_t)dst * 4 + head], p);
        }
    }
}

// ---------------- prep: concat + all inits ----------------
__global__ void prep_kernel(const float* __restrict__ x_node,
                            const float* __restrict__ x_log,
                            const float* __restrict__ bias1)
{
    size_t idx = (size_t)blockIdx.x * blockDim.x + threadIdx.x;
    if (idx >= (size_t)NN_ * DIN) return;
    int i = (int)(idx >> 8), c = (int)(idx & 255);
    g_node[idx] = (c < 128) ? x_node[(size_t)i * 128 + c]
                            : x_log[(size_t)i * 128 + (c - 128)];
    g_nodeout[idx] = bias1[c];
    if (idx < NN_ * 4) { g_amax1[idx] = -FLT_MAX; g_den1[idx] = 0.f; }
    if (idx < (size_t)E1_ * 4) { g_amax2[idx] = -FLT_MAX; g_den2[idx] = 0.f; }
}

// ---------------- layer-1 softmax + aggregate ----------------
__global__ void exp1_kernel(const int* __restrict__ adj) {
    int idx = blockIdx.x * blockDim.x + threadIdx.x;
    if (idx >= E1_ * 4) return;
    int e = idx >> 2, h = idx & 3;
    int dst = adj[E1_ + e];
    float ex = expf(g_alpha1[idx] - g_amax1[dst * 4 + h]);
    g_alpha1[idx] = ex;
    atomicAdd(&g_den1[dst * 4 + h], ex);
}

// warp per edge, float4 lanes, v4 reductions. lane l covers channels 4l and 128+4l.
__global__ __launch_bounds__(256) void agg1_kernel(const int* __restrict__ adj) {
    int warp = (blockIdx.x * blockDim.x + threadIdx.x) >> 5;
    int lane = threadIdx.x & 31;
    if (warp >= E1_) return;
    int src = adj[warp], dst = adj[E1_ + warp];
    int h0 = lane >> 4;           // head of channels [4l .. 4l+3]   (l<16 -> h0..1)
    float a0 = g_alpha1[(size_t)warp * 4 + h0]     / (g_den1[(size_t)dst * 4 + h0]     + EPSV);
    float a1 = g_alpha1[(size_t)warp * 4 + 2 + h0] / (g_den1[(size_t)dst * 4 + 2 + h0] + EPSV);
    const float* xl = g_xl + (size_t)src * DIN;
    float* out = g_nodeout + (size_t)dst * DIN;
    float4 v0 = *(const float4*)&xl[lane * 4];
    float4 v1 = *(const float4*)&xl[128 + lane * 4];
    red_add_v4(&out[lane * 4],       make_float4(a0 * v0.x, a0 * v0.y, a0 * v0.z, a0 * v0.w));
    red_add_v4(&out[128 + lane * 4], make_float4(a1 * v1.x, a1 * v1.y, a1 * v1.z, a1 * v1.w));
}

// ---------------- layer-2 edge kernels ----------------
// warp per edge; lane l covers channels [4l..4l+3], head = l>>3 (8-lane groups)
__global__ __launch_bounds__(256) void alpha2_kernel(const int* __restrict__ adj,
                                                     const int* __restrict__ efea,
                                                     const float* __restrict__ att)
{
    int warp = (blockIdx.x * blockDim.x + threadIdx.x) >> 5;
    int lane = threadIdx.x & 31;
    if (warp >= E2_) return;
    int src = adj[warp], dst = adj[E2_ + warp];
    int ef = efea[warp];
    float4 xlv = *(const float4*)&g_xl2  [(size_t)src * DED + lane * 4];
    float4 xrv = *(const float4*)&g_xr2  [(size_t)dst * DED + lane * 4];
    float4 eev = *(const float4*)&g_gfeat[(size_t)ef  * DED + lane * 4];
    float4 av  = *(const float4*)&att[lane * 4];
    float p;
    p  = lrelu02(xlv.x + xrv.x + eev.x) * av.x;
    p += lrelu02(xlv.y + xrv.y + eev.y) * av.y;
    p += lrelu02(xlv.z + xrv.z + eev.z) * av.z;
    p += lrelu02(xlv.w + xrv.w + eev.w) * av.w;
#pragma unroll
    for (int off = 4; off > 0; off >>= 1)
        p += __shfl_xor_sync(0xffffffff, p, off);
    if ((lane & 7) == 0) {
        int head = lane >> 3;
        g_alpha2[(size_t)warp * 4 + head] = p;
        atomicMaxFloat(&g_amax2[(size_t)dst * 4 + head], p);
    }
}

__global__ void exp2_kernel(const int* __restrict__ adj) {
    size_t idx = (size_t)blockIdx.x * blockDim.x + threadIdx.x;
    if (idx >= (size_t)E2_ * 4) return;
    int e = (int)(idx >> 2), h = (int)(idx & 3);
    int dst = adj[E2_ + e];
    float ex = expf(g_alpha2[idx] - g_amax2[(size_t)dst * 4 + h]);
    g_alpha2[idx] = ex;
    atomicAdd(&g_den2[(size_t)dst * 4 + h], ex);
}

__global__ void out_split_kernel(float* __restrict__ out, const float* __restrict__ bias2) {
    size_t idx = (size_t)blockIdx.x * blockDim.x + threadIdx.x;
    const size_t XN = (size_t)NN_ * 128;
    const size_t XT = (size_t)E1_ * 128;
    if (idx >= XN + XT + XN) return;
    if (idx < XN) {
        int i = (int)(idx >> 7), c = (int)(idx & 127);
        out[idx] = g_nodeout[(size_t)i * DIN + c];
    } else if (idx < XN + XT) {
        out[idx] = bias2[idx & 127];
    } else {
        size_t r = idx - (XN + XT);
        int i = (int)(r >> 7), c = (int)(r & 127);
        out[idx] = g_nodeout[(size_t)i * DIN + 128 + c];
    }
}

__global__ __launch_bounds__(256) void agg2_kernel(const int* __restrict__ adj,
                                                   float* __restrict__ out_xt)
{
    int warp = (blockIdx.x * blockDim.x + threadIdx.x) >> 5;
    int lane = threadIdx.x & 31;
    if (warp >= E2_) return;
    int src = adj[warp], dst = adj[E2_ + warp];
    int h = lane >> 3;
    float a = g_alpha2[(size_t)warp * 4 + h] / (g_den2[(size_t)dst * 4 + h] + EPSV);
    float4 v = *(const float4*)&g_xl2[(size_t)src * DED + lane * 4];
    red_add_v4(&out_xt[(size_t)dst * DED + lane * 4],
               make_float4(a * v.x, a * v.y, a * v.z, a * v.w));
}

// ---------------- launch ----------------
extern "C" void kernel_launch(void* const* d_in, const int* in_sizes, int n_in,
                              void* d_out, int out_size)
{
    const float* x_node   = (const float*)d_in[0];
    const float* x_trace  = (const float*)d_in[1];
    const float* x_log    = (const float*)d_in[2];
    const int*   node_adj = (const int*)d_in[3];
    const int*   edge_adj = (const int*)d_in[4];
    const int*   edge_efea= (const int*)d_in[5];
    const float* n2n_Wl   = (const float*)d_in[6];
    const float* n2n_bl   = (const float*)d_in[7];
    const float* n2n_Wr   = (const float*)d_in[8];
    const float* n2n_br   = (const float*)d_in[9];
    const float* n2n_We   = (const float*)d_in[10];
    const float* n2n_att  = (const float*)d_in[11];
    const float* n2n_bias = (const float*)d_in[12];
    const float* e2n_Wl   = (const float*)d_in[13];
    const float* e2n_bl   = (const float*)d_in[14];
    const float* e2n_Wr   = (const float*)d_in[15];
    const float* e2n_br   = (const float*)d_in[16];
    const float* e2n_We   = (const float*)d_in[17];
    const float* e2n_att  = (const float*)d_in[18];
    const float* e2n_bias = (const float*)d_in[19];
    float* out = (float*)d_out;

    float* p_node;    cudaGetSymbolAddress((void**)&p_node,    g_node);
    float* p_xl;      cudaGetSymbolAddress((void**)&p_xl,      g_xl);
    float* p_xr;      cudaGetSymbolAddress((void**)&p_xr,      g_xr);
    float* p_nodeout; cudaGetSymbolAddress((void**)&p_nodeout, g_nodeout);
    float* p_xl2;     cudaGetSymbolAddress((void**)&p_xl2,     g_xl2);
    float* p_xr2;     cudaGetSymbolAddress((void**)&p_xr2,     g_xr2);
    float* p_g;       cudaGetSymbolAddress((void**)&p_g,       g_gfeat);

    const int SMEM_PIPE  = 2 * STG * 4;          // 71680 (covers ET 128*132*4=67584 too)
    static int attr_done = 0;
    if (!attr_done) {
        cudaFuncSetAttribute(gemm_pipe, cudaFuncAttributeMaxDynamicSharedMemorySize, SMEM_PIPE);
        cudaFuncSetAttribute(gemm_alpha1_fused, cudaFuncAttributeMaxDynamicSharedMemorySize, SMEM_PIPE);
        attr_done = 1;
    }

    // 1: prep (concat + softmax inits + nodeout=bias)
    prep_kernel<<<(NN_ * DIN) / 256, 256>>>(x_node, x_log, n2n_bias);

    // 2: xl/xr dual GEMM
    {
        dim3 gdim(DIN / TBN, NN_ / TBM, 2);
        gemm_pipe<<<gdim, 256, SMEM_PIPE>>>(p_node, n2n_Wl, n2n_Wr, n2n_bl, n2n_br,
                                            p_xl, p_xr, NN_, DIN, DIN);
    }
    // 3: xl2/xr2 dual GEMM (depends only on x_trace)
    {
        dim3 gdim(DED / TBN, E1_ / TBM, 2);
        gemm_pipe<<<gdim, 256, SMEM_PIPE>>>(x_trace, e2n_Wl, e2n_Wr, e2n_bl, e2n_br,
                                            p_xl2, p_xr2, E1_, DED, DED);
    }
    // 4: fused e1 GEMM + alpha1
    {
        dim3 gdim(DIN / TBN, E1_ / TBM);
        gemm_alpha1_fused<<<gdim, 256, SMEM_PIPE>>>(x_trace, n2n_We, node_adj, n2n_att);
    }
    // 5-6: layer-1 softmax + aggregate
    exp1_kernel<<<(E1_ * 4) / 256, 256>>>(node_adj);
    agg1_kernel<<<E1_ / 8, 256>>>(node_adj);

    // 7: gfeat = node_out @ We2
    {
        dim3 gdim(DED / TBN, NN_ / TBM, 1);
        gemm_pipe<<<gdim, 256, SMEM_PIPE>>>(p_nodeout, e2n_We, e2n_We, nullptr, nullptr,
                                            p_g, p_g, NN_, DED, DIN);
    }
    // 8-9: layer-2 attention + softmax
    alpha2_kernel<<<E2_ / 8, 256>>>(edge_adj, edge_efea, e2n_att);
    exp2_kernel<<<(E2_ * 4) / 256, 256>>>(edge_adj);

    // 10-11: outputs
    {
        size_t total = (size_t)NN_ * 128 * 2 + (size_t)E1_ * 128;
        out_split_kernel<<<(unsigned)((total + 255) / 256), 256>>>(out, e2n_bias);
    }
    agg2_kernel<<<E2_ / 8, 256>>>(edge_adj, out + (size_t)NN_ * 128);
}